// round 2
// baseline (speedup 1.0000x reference)
#include <cuda_runtime.h>
#include <math.h>
#include <stdint.h>

// ---------------- problem constants ----------------
#define B_TOK 4096
#define DIN   512
#define PP    1024
#define HH    2048
#define EE    8
#define HSH   4096
#define OUTN  29
#define CAP   4096   // max tokens per expert (top-k indices are distinct -> <= B)

// ---------------- scratch (device globals; no allocation APIs) ----------------
__device__ float g_p   [B_TOK * PP];          // projected input        [4096,1024]
__device__ float g_h   [EE * CAP * HH];       // expert fc1 out         [32768,2048]
__device__ float g_eo  [EE * CAP * PP];       // expert fc2 out         [32768,1024]
__device__ float g_moe [B_TOK * PP];          // combined MoE out
__device__ float g_sg  [B_TOK * HSH];         // silu(p@sg_w+b)
__device__ float g_su  [B_TOK * HSH];         // gate*up
__device__ float g_comb[B_TOK * PP];          // moe + shared
__device__ float g_hid1[B_TOK * HH];
__device__ float g_hid2[B_TOK * HH];
__device__ int   g_counts[EE];
__device__ int   g_slot_token[EE * CAP];
__device__ int   g_pair_slot [B_TOK * 2];
__device__ float g_pair_gate [B_TOK * 2];

__device__ __forceinline__ float silu_f(float x) { return x / (1.0f + expf(-x)); }

// ---------------- dense SGEMM: C = epi(A[M,K] @ B[K,N] + bias[N]) ----------------
// MODE: 0 = +bias ; 1 = silu(+bias) ; 2 = (+bias)*D ; 3 = (+bias)+D
#define BM 128
#define BN 128
#define BKD 8
#define TM 8
#define TN 8

template<int MODE>
__global__ __launch_bounds__(256)
void sgemm_k(const float* __restrict__ A, const float* __restrict__ Bm,
             const float* __restrict__ bias, const float* __restrict__ D,
             float* __restrict__ C, int M, int N, int K)
{
    __shared__ float As[BKD][BM];
    __shared__ float Bs[BKD][BN];
    const int tid  = threadIdx.x;
    const int row0 = blockIdx.y * BM;
    const int col0 = blockIdx.x * BN;
    const int tM = tid >> 4;    // 0..15
    const int tN = tid & 15;    // 0..15

    const int aRow  = tid >> 1;
    const int aCol4 = (tid & 1) * 4;
    const int bRow  = tid >> 5;
    const int bCol4 = (tid & 31) * 4;

    const float* Aptr = A + (size_t)(row0 + aRow) * K + aCol4;
    const float* Bptr = Bm + (size_t)bRow * N + col0 + bCol4;

    float acc[TM][TN];
#pragma unroll
    for (int i = 0; i < TM; i++)
#pragma unroll
        for (int j = 0; j < TN; j++) acc[i][j] = 0.f;

    for (int k0 = 0; k0 < K; k0 += BKD) {
        float4 av = *(const float4*)Aptr;
        As[aCol4 + 0][aRow] = av.x; As[aCol4 + 1][aRow] = av.y;
        As[aCol4 + 2][aRow] = av.z; As[aCol4 + 3][aRow] = av.w;
        *(float4*)&Bs[bRow][bCol4] = *(const float4*)Bptr;
        __syncthreads();
#pragma unroll
        for (int kk = 0; kk < BKD; kk++) {
            float ra[TM], rb[TN];
#pragma unroll
            for (int i = 0; i < TM; i++) ra[i] = As[kk][tM * TM + i];
#pragma unroll
            for (int j = 0; j < TN; j++) rb[j] = Bs[kk][tN * TN + j];
#pragma unroll
            for (int i = 0; i < TM; i++)
#pragma unroll
                for (int j = 0; j < TN; j++) acc[i][j] += ra[i] * rb[j];
        }
        __syncthreads();
        Aptr += BKD;
        Bptr += (size_t)BKD * N;
    }

#pragma unroll
    for (int i = 0; i < TM; i++) {
        int r = row0 + tM * TM + i;
#pragma unroll
        for (int j = 0; j < TN; j++) {
            int c = col0 + tN * TN + j;
            float v = acc[i][j] + bias[c];
            if (MODE == 1) v = silu_f(v);
            if (MODE == 2) v = v * D[(size_t)r * N + c];
            if (MODE == 3) v = v + D[(size_t)r * N + c];
            C[(size_t)r * N + c] = v;
        }
    }
}

// ---------------- grouped GEMM over padded per-expert segments ----------------
// GATHER=true : A row i = Abase[slot_token[e*CAP+m0+i]]  (stage 1, K=PP)
// GATHER=false: A row i = Abase[e*CAP+m0+i]              (stage 2, K=HH)
template<int MODE, bool GATHER>
__global__ __launch_bounds__(256)
void ggemm_k(const float* __restrict__ Abase, const float* __restrict__ Wbase,
             const float* __restrict__ biasBase, float* __restrict__ Cbase,
             const int* __restrict__ counts, const int* __restrict__ slot_token,
             int N, int K)
{
    const int e   = blockIdx.z;
    const int cnt = counts[e];
    const int m0  = blockIdx.y * BM;
    if (m0 >= cnt) return;

    __shared__ float As[BKD][BM];
    __shared__ float Bs[BKD][BN];
    const int tid  = threadIdx.x;
    const int col0 = blockIdx.x * BN;
    const int tM = tid >> 4;
    const int tN = tid & 15;

    const float* Bm   = Wbase + (size_t)e * K * N;
    const float* bias = biasBase + (size_t)e * N;
    float*       C    = Cbase + (size_t)e * CAP * N;

    const int aRow  = tid >> 1;
    const int aCol4 = (tid & 1) * 4;
    const int bRow  = tid >> 5;
    const int bCol4 = (tid & 31) * 4;

    const float* Aptr;
    if (GATHER) {
        int tok = slot_token[e * CAP + m0 + aRow]; // stale beyond cnt -> still in [0,B), masked at store
        Aptr = Abase + (size_t)tok * K + aCol4;
    } else {
        Aptr = Abase + (size_t)(e * CAP + m0 + aRow) * K + aCol4;
    }
    const float* Bptr = Bm + (size_t)bRow * N + col0 + bCol4;

    float acc[TM][TN];
#pragma unroll
    for (int i = 0; i < TM; i++)
#pragma unroll
        for (int j = 0; j < TN; j++) acc[i][j] = 0.f;

    for (int k0 = 0; k0 < K; k0 += BKD) {
        float4 av = *(const float4*)Aptr;
        As[aCol4 + 0][aRow] = av.x; As[aCol4 + 1][aRow] = av.y;
        As[aCol4 + 2][aRow] = av.z; As[aCol4 + 3][aRow] = av.w;
        *(float4*)&Bs[bRow][bCol4] = *(const float4*)Bptr;
        __syncthreads();
#pragma unroll
        for (int kk = 0; kk < BKD; kk++) {
            float ra[TM], rb[TN];
#pragma unroll
            for (int i = 0; i < TM; i++) ra[i] = As[kk][tM * TM + i];
#pragma unroll
            for (int j = 0; j < TN; j++) rb[j] = Bs[kk][tN * TN + j];
#pragma unroll
            for (int i = 0; i < TM; i++)
#pragma unroll
                for (int j = 0; j < TN; j++) acc[i][j] += ra[i] * rb[j];
        }
        __syncthreads();
        Aptr += BKD;
        Bptr += (size_t)BKD * N;
    }

#pragma unroll
    for (int i = 0; i < TM; i++) {
        int r = m0 + tM * TM + i;
        if (r < cnt) {
#pragma unroll
            for (int j = 0; j < TN; j++) {
                int c = col0 + tN * TN + j;
                float v = acc[i][j] + bias[c];
                if (MODE == 1) v = silu_f(v);
                C[(size_t)r * N + c] = v;
            }
        }
    }
}

// ---------------- router: logits = p@Wg, top-2, renormalized softmax gates ----------------
__global__ void zero_counts_k(int* counts)
{
    if (threadIdx.x < EE) counts[threadIdx.x] = 0;
}

__global__ void router_k(const float* __restrict__ p, const float* __restrict__ Wg,
                         int* __restrict__ counts, int* __restrict__ slot_token,
                         int* __restrict__ pair_slot, float* __restrict__ pair_gate)
{
    const int t = blockIdx.x;
    const int tid = threadIdx.x; // 128 threads
    __shared__ float red[EE][128];
    float acc[EE];
#pragma unroll
    for (int e = 0; e < EE; e++) acc[e] = 0.f;
    const float* pr = p + (size_t)t * PP;
    for (int j = tid; j < PP; j += 128) {
        float pv = pr[j];
        const float* wg = Wg + (size_t)j * EE;
#pragma unroll
        for (int e = 0; e < EE; e++) acc[e] += pv * wg[e];
    }
#pragma unroll
    for (int e = 0; e < EE; e++) red[e][tid] = acc[e];
    __syncthreads();
    if (tid == 0) {
        float logit[EE];
        for (int e = 0; e < EE; e++) {
            float s = 0.f;
            for (int i = 0; i < 128; i++) s += red[e][i];
            logit[e] = s;
        }
        int i0 = 0;
        for (int e = 1; e < EE; e++) if (logit[e] > logit[i0]) i0 = e;
        int i1 = (i0 == 0) ? 1 : 0;
        for (int e = 0; e < EE; e++) {
            if (e == i0) continue;
            if (logit[e] > logit[i1]) i1 = e;
        }
        // gates = softmax over {l0, l1} (== normalized top-2 of full softmax)
        float g0 = 1.f / (1.f + expf(logit[i1] - logit[i0]));
        float g1 = 1.f - g0;
        int s0 = atomicAdd(&counts[i0], 1);
        int s1 = atomicAdd(&counts[i1], 1);
        slot_token[i0 * CAP + s0] = t;
        slot_token[i1 * CAP + s1] = t;
        pair_slot[2 * t]     = i0 * CAP + s0;
        pair_slot[2 * t + 1] = i1 * CAP + s1;
        pair_gate[2 * t]     = g0;
        pair_gate[2 * t + 1] = g1;
    }
}

// ---------------- combine: moe[t,:] = g0*eo[s0,:] + g1*eo[s1,:] ----------------
__global__ void combine_k(const float* __restrict__ eo, const int* __restrict__ pair_slot,
                          const float* __restrict__ pair_gate, float* __restrict__ moe)
{
    int idx = blockIdx.x * blockDim.x + threadIdx.x;
    if (idx >= B_TOK * PP) return;
    int t = idx >> 10;      // / PP
    int j = idx & (PP - 1); // % PP
    int s0 = pair_slot[2 * t], s1 = pair_slot[2 * t + 1];
    float g0 = pair_gate[2 * t], g1 = pair_gate[2 * t + 1];
    moe[idx] = g0 * eo[(size_t)s0 * PP + j] + g1 * eo[(size_t)s1 * PP + j];
}

// ---------------- head: out[t,o] = hid2[t,:] @ head_w[:,o] + head_b[o] ----------------
__global__ __launch_bounds__(256)
void head_k(const float* __restrict__ hid2, const float* __restrict__ head_w,
            const float* __restrict__ head_b, float* __restrict__ out)
{
    const int t = blockIdx.x;
    const int tid = threadIdx.x;
    const int lane = tid & 31;
    const int warp = tid >> 5; // 0..7
    __shared__ float row[HH];
    for (int i = tid; i < HH; i += 256) row[i] = hid2[(size_t)t * HH + i];
    __syncthreads();
#pragma unroll
    for (int oo = 0; oo < 4; oo++) {
        int o = warp + oo * 8;
        if (o >= OUTN) break;
        float s = 0.f;
        for (int i = lane; i < HH; i += 32) s += row[i] * head_w[(size_t)i * OUTN + o];
#pragma unroll
        for (int off = 16; off > 0; off >>= 1) s += __shfl_down_sync(0xFFFFFFFFu, s, off);
        if (lane == 0) out[(size_t)t * OUTN + o] = s + head_b[o];
    }
}

// ---------------- launch ----------------
template <typename T>
static T* symaddr(const void* sym)
{
    void* p = nullptr;
    cudaGetSymbolAddress(&p, sym);
    return (T*)p;
}

extern "C" void kernel_launch(void* const* d_in, const int* in_sizes, int n_in,
                              void* d_out, int out_size)
{
    const float* x      = (const float*)d_in[0];
    const float* Wproj  = (const float*)d_in[1];
    const float* bproj  = (const float*)d_in[2];
    const float* Wg     = (const float*)d_in[3];
    const float* W1     = (const float*)d_in[4];
    const float* b1     = (const float*)d_in[5];
    const float* W2     = (const float*)d_in[6];
    const float* b2     = (const float*)d_in[7];
    const float* sg_w   = (const float*)d_in[8];
    const float* sg_b   = (const float*)d_in[9];
    const float* su_w   = (const float*)d_in[10];
    const float* su_b   = (const float*)d_in[11];
    const float* sd_w   = (const float*)d_in[12];
    const float* sd_b   = (const float*)d_in[13];
    const float* m1_w   = (const float*)d_in[14];
    const float* m1_b   = (const float*)d_in[15];
    const float* m2_w   = (const float*)d_in[16];
    const float* m2_b   = (const float*)d_in[17];
    const float* head_w = (const float*)d_in[18];
    const float* head_b = (const float*)d_in[19];
    float* out = (float*)d_out;

    float* p_buf   = symaddr<float>(g_p);
    float* h_buf   = symaddr<float>(g_h);
    float* eo_buf  = symaddr<float>(g_eo);
    float* moe_buf = symaddr<float>(g_moe);
    float* sg_buf  = symaddr<float>(g_sg);
    float* su_buf  = symaddr<float>(g_su);
    float* cb_buf  = symaddr<float>(g_comb);
    float* h1_buf  = symaddr<float>(g_hid1);
    float* h2_buf  = symaddr<float>(g_hid2);
    int*   counts  = symaddr<int>(g_counts);
    int*   stok    = symaddr<int>(g_slot_token);
    int*   pslot   = symaddr<int>(g_pair_slot);
    float* pgate   = symaddr<float>(g_pair_gate);

    // 1. p = x @ Wproj + bproj                       [4096,1024] K=512
    sgemm_k<0><<<dim3(PP / BN, B_TOK / BM), 256>>>(x, Wproj, bproj, nullptr, p_buf,
                                                   B_TOK, PP, DIN);
    // 2. router: top-2 gating, scatter to per-expert slot lists
    zero_counts_k<<<1, 32>>>(counts);
    router_k<<<B_TOK, 128>>>(p_buf, Wg, counts, stok, pslot, pgate);
    // 3. expert fc1: h = silu(p_gathered @ W1[e] + b1[e])   N=2048 K=1024
    ggemm_k<1, true><<<dim3(HH / BN, CAP / BM, EE), 256>>>(p_buf, W1, b1, h_buf,
                                                           counts, stok, HH, PP);
    // 4. expert fc2: eo = h @ W2[e] + b2[e]                 N=1024 K=2048
    ggemm_k<0, false><<<dim3(PP / BN, CAP / BM, EE), 256>>>(h_buf, W2, b2, eo_buf,
                                                            counts, stok, PP, HH);
    // 5. weighted combine
    combine_k<<<(B_TOK * PP + 255) / 256, 256>>>(eo_buf, pslot, pgate, moe_buf);
    // 6. shared expert SwiGLU
    sgemm_k<1><<<dim3(HSH / BN, B_TOK / BM), 256>>>(p_buf, sg_w, sg_b, nullptr, sg_buf,
                                                    B_TOK, HSH, PP);
    sgemm_k<2><<<dim3(HSH / BN, B_TOK / BM), 256>>>(p_buf, su_w, su_b, sg_buf, su_buf,
                                                    B_TOK, HSH, PP);
    // 7. down proj + residual MoE add: comb = su @ sd_w + sd_b + moe
    sgemm_k<3><<<dim3(PP / BN, B_TOK / BM), 256>>>(su_buf, sd_w, sd_b, moe_buf, cb_buf,
                                                   B_TOK, PP, HSH);
    // 8. output MLP
    sgemm_k<1><<<dim3(HH / BN, B_TOK / BM), 256>>>(cb_buf, m1_w, m1_b, nullptr, h1_buf,
                                                   B_TOK, HH, PP);
    sgemm_k<0><<<dim3(HH / BN, B_TOK / BM), 256>>>(h1_buf, m2_w, m2_b, nullptr, h2_buf,
                                                   B_TOK, HH, HH);
    // 9. head
    head_k<<<B_TOK, 256>>>(h2_buf, head_w, head_b, out);
}

// round 4
// speedup vs baseline: 2.9691x; 2.9691x over previous
#include <cuda_runtime.h>
#include <cuda_bf16.h>
#include <math.h>
#include <stdint.h>

// ---------------- problem constants ----------------
#define B_TOK 4096
#define DIN   512
#define PP    1024
#define HH    2048
#define EE    8
#define HSH   4096
#define OUTN  29
#define CAP   4096

// ---------------- mma.sync GEMM tile config ----------------
#define BM 128
#define BN 128
#define BKC 32                 // bf16 k elems per chunk (64 bytes per row)
#define ROWB 80                // smem row stride bytes (64B data + 16B pad)
#define OFF_AH 0
#define OFF_AL (128 * ROWB)
#define OFF_BH (2 * 128 * ROWB)
#define OFF_BL (3 * 128 * ROWB)
#define STAGE_BYTES (4 * 128 * ROWB)     // 40960
#define NSTAGE 3
#define SMEM_BYTES (NSTAGE * STAGE_BYTES) // 122880

// ---------------- PTX helpers ----------------
__device__ __forceinline__ uint32_t smem_u32(const void* p) {
    uint32_t a;
    asm("{ .reg .u64 t; cvta.to.shared.u64 t, %1; cvt.u32.u64 %0, t; }" : "=r"(a) : "l"(p));
    return a;
}
#define CP16(dst, src) asm volatile("cp.async.cg.shared.global [%0], [%1], 16;" :: "r"(dst), "l"(src) : "memory")
#define CP_COMMIT()    asm volatile("cp.async.commit_group;" ::: "memory")

#define LDSM4(r, addr) \
    asm volatile("ldmatrix.sync.aligned.m8n8.x4.shared.b16 {%0,%1,%2,%3}, [%4];" \
        : "=r"((r)[0]), "=r"((r)[1]), "=r"((r)[2]), "=r"((r)[3]) : "r"(addr))

#define MMA_BF16(c, a, b0, b1) \
    asm volatile("mma.sync.aligned.m16n8k16.row.col.f32.bf16.bf16.f32 " \
        "{%0,%1,%2,%3}, {%4,%5,%6,%7}, {%8,%9}, {%0,%1,%2,%3};" \
        : "+f"((c)[0]), "+f"((c)[1]), "+f"((c)[2]), "+f"((c)[3]) \
        : "r"((a)[0]), "r"((a)[1]), "r"((a)[2]), "r"((a)[3]), "r"(b0), "r"(b1))

// ---------------- scratch (device globals) ----------------
#define DEV __device__ __align__(128)
DEV __nv_bfloat16 g_x_hi [B_TOK * DIN],   g_x_lo [B_TOK * DIN];
DEV __nv_bfloat16 g_p_hi [B_TOK * PP],    g_p_lo [B_TOK * PP];
DEV float         g_p32  [B_TOK * PP];
DEV __nv_bfloat16 g_ap_hi[EE * CAP * PP], g_ap_lo[EE * CAP * PP];
DEV __nv_bfloat16 g_h_hi [EE * CAP * HH], g_h_lo [EE * CAP * HH];
DEV float         g_eo32 [EE * CAP * PP];
DEV float         g_moe  [B_TOK * PP];
DEV float         g_sg32 [B_TOK * HSH];
DEV __nv_bfloat16 g_su_hi[B_TOK * HSH],   g_su_lo[B_TOK * HSH];
DEV __nv_bfloat16 g_cb_hi[B_TOK * PP],    g_cb_lo[B_TOK * PP];
DEV __nv_bfloat16 g_h1_hi[B_TOK * HH],    g_h1_lo[B_TOK * HH];
DEV float         g_h232 [B_TOK * HH];
DEV __nv_bfloat16 g_wp_hi [PP * DIN],     g_wp_lo [PP * DIN];
DEV __nv_bfloat16 g_w1_hi [EE * HH * PP], g_w1_lo [EE * HH * PP];
DEV __nv_bfloat16 g_w2_hi [EE * PP * HH], g_w2_lo [EE * PP * HH];
DEV __nv_bfloat16 g_sgw_hi[HSH * PP],     g_sgw_lo[HSH * PP];
DEV __nv_bfloat16 g_suw_hi[HSH * PP],     g_suw_lo[HSH * PP];
DEV __nv_bfloat16 g_sdw_hi[PP * HSH],     g_sdw_lo[PP * HSH];
DEV __nv_bfloat16 g_m1_hi [HH * PP],      g_m1_lo [HH * PP];
DEV __nv_bfloat16 g_m2_hi [HH * HH],      g_m2_lo [HH * HH];
DEV int   g_counts[EE];
DEV int   g_slot_token[EE * CAP];
DEV int   g_pair_slot[B_TOK * 2];
DEV float g_pair_gate[B_TOK * 2];

__device__ __forceinline__ float silu_f(float x) { return x / (1.0f + expf(-x)); }

// ---------------- stage fill (cp.async, 128 rows x 64B per matrix) ----------------
__device__ __forceinline__ void fill_stage(uint32_t st, int tid,
    const char* Ah, const char* Al, const char* Bh, const char* Bl,
    size_t Kb, long rowA0, long rowB0, size_t kByte)
{
#pragma unroll
    for (int i = 0; i < 2; i++) {
        int p = tid + (i << 8);
        int row = p >> 2, ch = p & 3;
        uint32_t d = st + row * ROWB + ch * 16;
        size_t sa = (size_t)(rowA0 + row) * Kb + kByte + ch * 16;
        CP16(d + OFF_AH, Ah + sa);
        CP16(d + OFF_AL, Al + sa);
        size_t sbo = (size_t)(rowB0 + row) * Kb + kByte + ch * 16;
        CP16(d + OFF_BH, Bh + sbo);
        CP16(d + OFF_BL, Bl + sbo);
    }
    CP_COMMIT();
}

// ---------------- bf16-split x3 GEMM on mma.sync ----------------
// C[M,N] = epi(A[M,K] @ B[N,K]^T + bias);  A,B given as hi/lo bf16 pairs.
// MODE: 0 = +bias ; 1 = silu(+bias) ; 2 = (+bias)*extra ; 3 = (+bias)+extra
template<int MODE>
__global__ __launch_bounds__(256, 1)
void mm_gemm(const __nv_bfloat16* __restrict__ Ahi, const __nv_bfloat16* __restrict__ Alo,
             const __nv_bfloat16* __restrict__ Bhi, const __nv_bfloat16* __restrict__ Blo,
             const float* __restrict__ bias, const float* __restrict__ extra,
             float* __restrict__ C32, __nv_bfloat16* __restrict__ Chi,
             __nv_bfloat16* __restrict__ Clo,
             const int* __restrict__ counts, int capRows, int N, int K)
{
    const int z  = blockIdx.z;
    const int m0 = blockIdx.y * BM;
    const int n0 = blockIdx.x * BN;
    int cnt = capRows;
    if (counts) { cnt = counts[z]; if (m0 >= cnt) return; }

    extern __shared__ __align__(128) char smem[];
    const uint32_t sb = smem_u32(smem);
    const int tid = threadIdx.x, lane = tid & 31, wid = tid >> 5;
    const int warp_m = wid & 1;      // 2 warps over M (64 rows each)
    const int warp_n = wid >> 1;     // 4 warps over N (32 cols each)

    const size_t Kb = (size_t)K * 2;
    const long rowA0 = (long)z * capRows + m0;
    const long rowB0 = (long)z * N + n0;
    const int  C = K / BKC;

    float acc[4][4][4];
#pragma unroll
    for (int i = 0; i < 4; i++)
#pragma unroll
        for (int j = 0; j < 4; j++)
#pragma unroll
            for (int q = 0; q < 4; q++) acc[i][j][q] = 0.f;

    const char* Ah = (const char*)Ahi; const char* Al = (const char*)Alo;
    const char* Bh = (const char*)Bhi; const char* Bl = (const char*)Blo;

    fill_stage(sb, tid, Ah, Al, Bh, Bl, Kb, rowA0, rowB0, 0);
    if (C > 1) fill_stage(sb + STAGE_BYTES, tid, Ah, Al, Bh, Bl, Kb, rowA0, rowB0, 64);
    if (C > 2) fill_stage(sb + 2 * STAGE_BYTES, tid, Ah, Al, Bh, Bl, Kb, rowA0, rowB0, 128);

    const int lm = lane & 15;               // row within 16-row ldmatrix group
    const int lkb = (lane >> 4) << 4;       // 0 or 16 byte k-offset

    for (int c = 0; c < C; c++) {
        if (c + 2 < C)      asm volatile("cp.async.wait_group 2;" ::: "memory");
        else if (c + 1 < C) asm volatile("cp.async.wait_group 1;" ::: "memory");
        else                asm volatile("cp.async.wait_group 0;" ::: "memory");
        __syncthreads();

        const uint32_t stg = sb + (c % NSTAGE) * STAGE_BYTES;
#pragma unroll
        for (int kk = 0; kk < 2; kk++) {
            const uint32_t kb = kk * 32 + lkb;
            uint32_t a_h[4][4], a_l[4][4], b_h[2][4], b_l[2][4];
#pragma unroll
            for (int mt = 0; mt < 4; mt++) {
                uint32_t ad = stg + (warp_m * 64 + mt * 16 + lm) * ROWB + kb;
                LDSM4(a_h[mt], ad + OFF_AH);
                LDSM4(a_l[mt], ad + OFF_AL);
            }
#pragma unroll
            for (int nt2 = 0; nt2 < 2; nt2++) {
                uint32_t bd = stg + (warp_n * 32 + nt2 * 16 + lm) * ROWB + kb;
                LDSM4(b_h[nt2], bd + OFF_BH);
                LDSM4(b_l[nt2], bd + OFF_BL);
            }
#pragma unroll
            for (int mt = 0; mt < 4; mt++)
#pragma unroll
                for (int nt = 0; nt < 4; nt++) {
                    const int n2 = nt >> 1, o = nt & 1;
                    MMA_BF16(acc[mt][nt], a_h[mt], b_h[n2][o], b_h[n2][o + 2]);
                    MMA_BF16(acc[mt][nt], a_h[mt], b_l[n2][o], b_l[n2][o + 2]);
                    MMA_BF16(acc[mt][nt], a_l[mt], b_h[n2][o], b_h[n2][o + 2]);
                }
        }
        __syncthreads();
        if (c + 3 < C)
            fill_stage(sb + (c % NSTAGE) * STAGE_BYTES, tid, Ah, Al, Bh, Bl,
                       Kb, rowA0, rowB0, (size_t)(c + 3) * 64);
    }

    // ---- epilogue: registers -> gmem ----
    const float* biasz = bias + (size_t)z * N;
#pragma unroll
    for (int mt = 0; mt < 4; mt++) {
#pragma unroll
        for (int half = 0; half < 2; half++) {
            const int rtile = warp_m * 64 + mt * 16 + (lane >> 2) + half * 8;
            if (m0 + rtile >= cnt) continue;
            const size_t gr = (size_t)z * capRows + m0 + rtile;
#pragma unroll
            for (int nt = 0; nt < 4; nt++) {
                const int col = n0 + warp_n * 32 + nt * 8 + (lane & 3) * 2;
                float v0 = acc[mt][nt][half * 2 + 0] + biasz[col];
                float v1 = acc[mt][nt][half * 2 + 1] + biasz[col + 1];
                if (MODE == 1) { v0 = silu_f(v0); v1 = silu_f(v1); }
                if (MODE == 2) {
                    const float2 e = *(const float2*)&extra[gr * N + col];
                    v0 *= e.x; v1 *= e.y;
                }
                if (MODE == 3) {
                    const float2 e = *(const float2*)&extra[gr * N + col];
                    v0 += e.x; v1 += e.y;
                }
                if (C32) { float2 w = {v0, v1}; *(float2*)&C32[gr * N + col] = w; }
                if (Chi) {
                    __nv_bfloat16 h0 = __float2bfloat16(v0);
                    __nv_bfloat16 h1 = __float2bfloat16(v1);
                    __nv_bfloat162 hp; hp.x = h0; hp.y = h1;
                    *(__nv_bfloat162*)&Chi[gr * N + col] = hp;
                    __nv_bfloat162 lp;
                    lp.x = __float2bfloat16(v0 - __bfloat162float(h0));
                    lp.y = __float2bfloat16(v1 - __bfloat162float(h1));
                    *(__nv_bfloat162*)&Clo[gr * N + col] = lp;
                }
            }
        }
    }
}

// ---------------- small kernels ----------------
__global__ void conv_split_k(const float* __restrict__ in, __nv_bfloat16* __restrict__ hi,
                             __nv_bfloat16* __restrict__ lo, size_t n)
{
    size_t i = (size_t)blockIdx.x * blockDim.x + threadIdx.x;
    if (i >= n) return;
    float v = in[i];
    __nv_bfloat16 h = __float2bfloat16(v);
    hi[i] = h;
    lo[i] = __float2bfloat16(v - __bfloat162float(h));
}

// W [z, K, N] row-major -> out [(z*N + n), k]  (transpose + split)
__global__ void convT_k(const float* __restrict__ W, __nv_bfloat16* __restrict__ hi,
                        __nv_bfloat16* __restrict__ lo, int K, int N)
{
    __shared__ float t[32][33];
    const int n0 = blockIdx.x * 32, k0 = blockIdx.y * 32;
    const float* Wz = W + (size_t)blockIdx.z * K * N;
    for (int i = threadIdx.y; i < 32; i += 8)
        t[i][threadIdx.x] = Wz[(size_t)(k0 + i) * N + n0 + threadIdx.x];
    __syncthreads();
    for (int i = threadIdx.y; i < 32; i += 8) {
        size_t o = ((size_t)blockIdx.z * N + n0 + i) * K + k0 + threadIdx.x;
        float v = t[threadIdx.x][i];
        __nv_bfloat16 h = __float2bfloat16(v);
        hi[o] = h;
        lo[o] = __float2bfloat16(v - __bfloat162float(h));
    }
}

__global__ void zero_counts_k(int* counts) { if (threadIdx.x < EE) counts[threadIdx.x] = 0; }

__global__ void router_k(const float* __restrict__ p, const float* __restrict__ Wg,
                         int* __restrict__ counts, int* __restrict__ slot_token,
                         int* __restrict__ pair_slot, float* __restrict__ pair_gate)
{
    const int t = blockIdx.x;
    const int tid = threadIdx.x; // 128
    __shared__ float red[EE][128];
    float acc[EE];
#pragma unroll
    for (int e = 0; e < EE; e++) acc[e] = 0.f;
    const float* pr = p + (size_t)t * PP;
    for (int j = tid; j < PP; j += 128) {
        float pv = pr[j];
        const float* wg = Wg + (size_t)j * EE;
#pragma unroll
        for (int e = 0; e < EE; e++) acc[e] += pv * wg[e];
    }
#pragma unroll
    for (int e = 0; e < EE; e++) red[e][tid] = acc[e];
    __syncthreads();
    if (tid == 0) {
        float logit[EE];
        for (int e = 0; e < EE; e++) {
            float s = 0.f;
            for (int i = 0; i < 128; i++) s += red[e][i];
            logit[e] = s;
        }
        int i0 = 0;
        for (int e = 1; e < EE; e++) if (logit[e] > logit[i0]) i0 = e;
        int i1 = (i0 == 0) ? 1 : 0;
        for (int e = 0; e < EE; e++) {
            if (e == i0) continue;
            if (logit[e] > logit[i1]) i1 = e;
        }
        float g0 = 1.f / (1.f + expf(logit[i1] - logit[i0]));
        float g1 = 1.f - g0;
        int s0 = atomicAdd(&counts[i0], 1);
        int s1 = atomicAdd(&counts[i1], 1);
        slot_token[i0 * CAP + s0] = t;
        slot_token[i1 * CAP + s1] = t;
        pair_slot[2 * t]     = i0 * CAP + s0;
        pair_slot[2 * t + 1] = i1 * CAP + s1;
        pair_gate[2 * t]     = g0;
        pair_gate[2 * t + 1] = g1;
    }
}

__global__ void pack_k(const __nv_bfloat16* __restrict__ ph, const __nv_bfloat16* __restrict__ pl,
                       const int* __restrict__ stok, const int* __restrict__ counts,
                       __nv_bfloat16* __restrict__ aph, __nv_bfloat16* __restrict__ apl)
{
    const int slot = blockIdx.x;
    const int e = slot >> 12;
    if ((slot & (CAP - 1)) >= counts[e]) return;
    const int tok = stok[slot];
    const float4* s1 = (const float4*)(ph + (size_t)tok * PP);
    const float4* s2 = (const float4*)(pl + (size_t)tok * PP);
    float4* d1 = (float4*)(aph + (size_t)slot * PP);
    float4* d2 = (float4*)(apl + (size_t)slot * PP);
    const int t = threadIdx.x;
    d1[t] = s1[t];
    d2[t] = s2[t];
}

__global__ void combine_k(const float* __restrict__ eo, const int* __restrict__ pair_slot,
                          const float* __restrict__ pair_gate, float* __restrict__ moe)
{
    int idx = blockIdx.x * blockDim.x + threadIdx.x;
    if (idx >= B_TOK * PP) return;
    int t = idx >> 10, j = idx & (PP - 1);
    int s0 = pair_slot[2 * t], s1 = pair_slot[2 * t + 1];
    float g0 = pair_gate[2 * t], g1 = pair_gate[2 * t + 1];
    moe[idx] = g0 * eo[(size_t)s0 * PP + j] + g1 * eo[(size_t)s1 * PP + j];
}

__global__ __launch_bounds__(256)
void head_k(const float* __restrict__ hid2, const float* __restrict__ head_w,
            const float* __restrict__ head_b, float* __restrict__ out)
{
    const int t = blockIdx.x, tid = threadIdx.x;
    const int lane = tid & 31, warp = tid >> 5;
    __shared__ float row[HH];
    for (int i = tid; i < HH; i += 256) row[i] = hid2[(size_t)t * HH + i];
    __syncthreads();
#pragma unroll
    for (int oo = 0; oo < 4; oo++) {
        int o = warp + oo * 8;
        if (o >= OUTN) break;
        float s = 0.f;
        for (int i = lane; i < HH; i += 32) s += row[i] * head_w[(size_t)i * OUTN + o];
#pragma unroll
        for (int off = 16; off > 0; off >>= 1) s += __shfl_down_sync(0xFFFFFFFFu, s, off);
        if (lane == 0) out[(size_t)t * OUTN + o] = s + head_b[o];
    }
}

// ---------------- launch ----------------
template <typename T>
static T* symaddr(const void* sym) { void* p = nullptr; cudaGetSymbolAddress(&p, sym); return (T*)p; }

extern "C" void kernel_launch(void* const* d_in, const int* in_sizes, int n_in,
                              void* d_out, int out_size)
{
    const float* x      = (const float*)d_in[0];
    const float* Wproj  = (const float*)d_in[1];
    const float* bproj  = (const float*)d_in[2];
    const float* Wg     = (const float*)d_in[3];
    const float* W1     = (const float*)d_in[4];
    const float* b1     = (const float*)d_in[5];
    const float* W2     = (const float*)d_in[6];
    const float* b2     = (const float*)d_in[7];
    const float* sg_w   = (const float*)d_in[8];
    const float* sg_b   = (const float*)d_in[9];
    const float* su_w   = (const float*)d_in[10];
    const float* su_b   = (const float*)d_in[11];
    const float* sd_w   = (const float*)d_in[12];
    const float* sd_b   = (const float*)d_in[13];
    const float* m1_w   = (const float*)d_in[14];
    const float* m1_b   = (const float*)d_in[15];
    const float* m2_w   = (const float*)d_in[16];
    const float* m2_b   = (const float*)d_in[17];
    const float* head_w = (const float*)d_in[18];
    const float* head_b = (const float*)d_in[19];
    float* out = (float*)d_out;

    static bool attr_done = false;
    if (!attr_done) {
        cudaFuncSetAttribute(mm_gemm<0>, cudaFuncAttributeMaxDynamicSharedMemorySize, SMEM_BYTES);
        cudaFuncSetAttribute(mm_gemm<1>, cudaFuncAttributeMaxDynamicSharedMemorySize, SMEM_BYTES);
        cudaFuncSetAttribute(mm_gemm<2>, cudaFuncAttributeMaxDynamicSharedMemorySize, SMEM_BYTES);
        cudaFuncSetAttribute(mm_gemm<3>, cudaFuncAttributeMaxDynamicSharedMemorySize, SMEM_BYTES);
        attr_done = true;
    }

    __nv_bfloat16 *x_hi = symaddr<__nv_bfloat16>(g_x_hi),  *x_lo = symaddr<__nv_bfloat16>(g_x_lo);
    __nv_bfloat16 *p_hi = symaddr<__nv_bfloat16>(g_p_hi),  *p_lo = symaddr<__nv_bfloat16>(g_p_lo);
    float *p32  = symaddr<float>(g_p32);
    __nv_bfloat16 *ap_hi = symaddr<__nv_bfloat16>(g_ap_hi), *ap_lo = symaddr<__nv_bfloat16>(g_ap_lo);
    __nv_bfloat16 *h_hi  = symaddr<__nv_bfloat16>(g_h_hi),  *h_lo  = symaddr<__nv_bfloat16>(g_h_lo);
    float *eo32 = symaddr<float>(g_eo32);
    float *moe  = symaddr<float>(g_moe);
    float *sg32 = symaddr<float>(g_sg32);
    __nv_bfloat16 *su_hi = symaddr<__nv_bfloat16>(g_su_hi), *su_lo = symaddr<__nv_bfloat16>(g_su_lo);
    __nv_bfloat16 *cb_hi = symaddr<__nv_bfloat16>(g_cb_hi), *cb_lo = symaddr<__nv_bfloat16>(g_cb_lo);
    __nv_bfloat16 *h1_hi = symaddr<__nv_bfloat16>(g_h1_hi), *h1_lo = symaddr<__nv_bfloat16>(g_h1_lo);
    float *h232 = symaddr<float>(g_h232);
    __nv_bfloat16 *wp_hi = symaddr<__nv_bfloat16>(g_wp_hi), *wp_lo = symaddr<__nv_bfloat16>(g_wp_lo);
    __nv_bfloat16 *w1_hi = symaddr<__nv_bfloat16>(g_w1_hi), *w1_lo = symaddr<__nv_bfloat16>(g_w1_lo);
    __nv_bfloat16 *w2_hi = symaddr<__nv_bfloat16>(g_w2_hi), *w2_lo = symaddr<__nv_bfloat16>(g_w2_lo);
    __nv_bfloat16 *sgw_hi = symaddr<__nv_bfloat16>(g_sgw_hi), *sgw_lo = symaddr<__nv_bfloat16>(g_sgw_lo);
    __nv_bfloat16 *suw_hi = symaddr<__nv_bfloat16>(g_suw_hi), *suw_lo = symaddr<__nv_bfloat16>(g_suw_lo);
    __nv_bfloat16 *sdw_hi = symaddr<__nv_bfloat16>(g_sdw_hi), *sdw_lo = symaddr<__nv_bfloat16>(g_sdw_lo);
    __nv_bfloat16 *m1_hi = symaddr<__nv_bfloat16>(g_m1_hi), *m1_lo = symaddr<__nv_bfloat16>(g_m1_lo);
    __nv_bfloat16 *m2_hi = symaddr<__nv_bfloat16>(g_m2_hi), *m2_lo = symaddr<__nv_bfloat16>(g_m2_lo);
    int *counts = symaddr<int>(g_counts);
    int *stok   = symaddr<int>(g_slot_token);
    int *pslot  = symaddr<int>(g_pair_slot);
    float *pgate = symaddr<float>(g_pair_gate);

    // ---- split inputs / transpose+split weights ----
    conv_split_k<<<(B_TOK * DIN + 255) / 256, 256>>>(x, x_hi, x_lo, (size_t)B_TOK * DIN);
    convT_k<<<dim3(PP / 32, DIN / 32, 1),  dim3(32, 8)>>>(Wproj, wp_hi, wp_lo, DIN, PP);
    convT_k<<<dim3(HH / 32, PP / 32, EE),  dim3(32, 8)>>>(W1, w1_hi, w1_lo, PP, HH);
    convT_k<<<dim3(PP / 32, HH / 32, EE),  dim3(32, 8)>>>(W2, w2_hi, w2_lo, HH, PP);
    convT_k<<<dim3(HSH / 32, PP / 32, 1),  dim3(32, 8)>>>(sg_w, sgw_hi, sgw_lo, PP, HSH);
    convT_k<<<dim3(HSH / 32, PP / 32, 1),  dim3(32, 8)>>>(su_w, suw_hi, suw_lo, PP, HSH);
    convT_k<<<dim3(PP / 32, HSH / 32, 1),  dim3(32, 8)>>>(sd_w, sdw_hi, sdw_lo, HSH, PP);
    convT_k<<<dim3(HH / 32, PP / 32, 1),   dim3(32, 8)>>>(m1_w, m1_hi, m1_lo, PP, HH);
    convT_k<<<dim3(HH / 32, HH / 32, 1),   dim3(32, 8)>>>(m2_w, m2_hi, m2_lo, HH, HH);

    // 1. p = x @ Wproj + bproj  (fp32 for router + bf16 split for downstream)
    mm_gemm<0><<<dim3(PP / BN, B_TOK / BM, 1), 256, SMEM_BYTES>>>(
        x_hi, x_lo, wp_hi, wp_lo, bproj, nullptr, p32, p_hi, p_lo,
        nullptr, B_TOK, PP, DIN);
    // 2. router + pack
    zero_counts_k<<<1, 32>>>(counts);
    router_k<<<B_TOK, 128>>>(p32, Wg, counts, stok, pslot, pgate);
    pack_k<<<EE * CAP, 128>>>(p_hi, p_lo, stok, counts, ap_hi, ap_lo);
    // 3. expert fc1: h = silu(ap @ W1^T + b1)
    mm_gemm<1><<<dim3(HH / BN, CAP / BM, EE), 256, SMEM_BYTES>>>(
        ap_hi, ap_lo, w1_hi, w1_lo, b1, nullptr, nullptr, h_hi, h_lo,
        counts, CAP, HH, PP);
    // 4. expert fc2: eo = h @ W2^T + b2
    mm_gemm<0><<<dim3(PP / BN, CAP / BM, EE), 256, SMEM_BYTES>>>(
        h_hi, h_lo, w2_hi, w2_lo, b2, nullptr, eo32, nullptr, nullptr,
        counts, CAP, PP, HH);
    // 5. combine
    combine_k<<<(B_TOK * PP + 255) / 256, 256>>>(eo32, pslot, pgate, moe);
    // 6. shared SwiGLU
    mm_gemm<1><<<dim3(HSH / BN, B_TOK / BM, 1), 256, SMEM_BYTES>>>(
        p_hi, p_lo, sgw_hi, sgw_lo, sg_b, nullptr, sg32, nullptr, nullptr,
        nullptr, B_TOK, HSH, PP);
    mm_gemm<2><<<dim3(HSH / BN, B_TOK / BM, 1), 256, SMEM_BYTES>>>(
        p_hi, p_lo, suw_hi, suw_lo, su_b, sg32, nullptr, su_hi, su_lo,
        nullptr, B_TOK, HSH, PP);
    // 7. down proj + moe residual
    mm_gemm<3><<<dim3(PP / BN, B_TOK / BM, 1), 256, SMEM_BYTES>>>(
        su_hi, su_lo, sdw_hi, sdw_lo, sd_b, moe, nullptr, cb_hi, cb_lo,
        nullptr, B_TOK, PP, HSH);
    // 8. output MLP
    mm_gemm<1><<<dim3(HH / BN, B_TOK / BM, 1), 256, SMEM_BYTES>>>(
        cb_hi, cb_lo, m1_hi, m1_lo, m1_b, nullptr, nullptr, h1_hi, h1_lo,
        nullptr, B_TOK, HH, PP);
    mm_gemm<0><<<dim3(HH / BN, B_TOK / BM, 1), 256, SMEM_BYTES>>>(
        h1_hi, h1_lo, m2_hi, m2_lo, m2_b, nullptr, h232, nullptr, nullptr,
        nullptr, B_TOK, HH, HH);
    // 9. head
    head_k<<<B_TOK, 256>>>(h232, head_w, head_b, out);
}

// round 5
// speedup vs baseline: 3.0832x; 1.0384x over previous
#include <cuda_runtime.h>
#include <cuda_bf16.h>
#include <math.h>
#include <stdint.h>

// ---------------- problem constants ----------------
#define B_TOK 4096
#define DIN   512
#define PP    1024
#define HH    2048
#define EE    8
#define HSH   4096
#define OUTN  29
#define CAP   4096

// ---------------- mma.sync GEMM tile config ----------------
#define BM 128
#define BN 256
#define BKC 32                     // bf16 k elems per chunk (64 bytes)
#define ROWB 80                    // smem row stride (64B data + 16B pad)
#define OFF_AH 0
#define OFF_AL (128 * ROWB)
#define OFF_BH (256 * ROWB)
#define OFF_BL (256 * ROWB + 256 * ROWB)
#define STAGE_BYTES (768 * ROWB)   // 61440
#define NSTAGE 3
#define SMEM_BYTES (NSTAGE * STAGE_BYTES) // 184320

// ---------------- PTX helpers ----------------
__device__ __forceinline__ uint32_t smem_u32(const void* p) {
    uint32_t a;
    asm("{ .reg .u64 t; cvta.to.shared.u64 t, %1; cvt.u32.u64 %0, t; }" : "=r"(a) : "l"(p));
    return a;
}
#define CP16(dst, src) asm volatile("cp.async.cg.shared.global [%0], [%1], 16;" :: "r"(dst), "l"(src) : "memory")
#define CP_COMMIT()    asm volatile("cp.async.commit_group;" ::: "memory")

#define LDSM4(r, addr) \
    asm volatile("ldmatrix.sync.aligned.m8n8.x4.shared.b16 {%0,%1,%2,%3}, [%4];" \
        : "=r"((r)[0]), "=r"((r)[1]), "=r"((r)[2]), "=r"((r)[3]) : "r"(addr))

#define MMA_BF16(c, a, b0, b1) \
    asm volatile("mma.sync.aligned.m16n8k16.row.col.f32.bf16.bf16.f32 " \
        "{%0,%1,%2,%3}, {%4,%5,%6,%7}, {%8,%9}, {%0,%1,%2,%3};" \
        : "+f"((c)[0]), "+f"((c)[1]), "+f"((c)[2]), "+f"((c)[3]) \
        : "r"((a)[0]), "r"((a)[1]), "r"((a)[2]), "r"((a)[3]), "r"(b0), "r"(b1))

// ---------------- scratch (device globals) ----------------
#define DEV __device__ __align__(128)
DEV __nv_bfloat16 g_x_hi [B_TOK * DIN],   g_x_lo [B_TOK * DIN];
DEV __nv_bfloat16 g_p_hi [B_TOK * PP],    g_p_lo [B_TOK * PP];
DEV float         g_p32  [B_TOK * PP];
DEV __nv_bfloat16 g_ap_hi[EE * CAP * PP], g_ap_lo[EE * CAP * PP];
DEV __nv_bfloat16 g_h_hi [EE * CAP * HH], g_h_lo [EE * CAP * HH];
DEV float         g_eo32 [EE * CAP * PP];
DEV float         g_moe  [B_TOK * PP];
DEV float         g_sg32 [B_TOK * HSH];
DEV __nv_bfloat16 g_su_hi[B_TOK * HSH],   g_su_lo[B_TOK * HSH];
DEV __nv_bfloat16 g_cb_hi[B_TOK * PP],    g_cb_lo[B_TOK * PP];
DEV __nv_bfloat16 g_h1_hi[B_TOK * HH],    g_h1_lo[B_TOK * HH];
DEV float         g_h232 [B_TOK * HH];
DEV __nv_bfloat16 g_wp_hi [PP * DIN],     g_wp_lo [PP * DIN];
DEV __nv_bfloat16 g_w1_hi [EE * HH * PP], g_w1_lo [EE * HH * PP];
DEV __nv_bfloat16 g_w2_hi [EE * PP * HH], g_w2_lo [EE * PP * HH];
DEV __nv_bfloat16 g_sgw_hi[HSH * PP],     g_sgw_lo[HSH * PP];
DEV __nv_bfloat16 g_suw_hi[HSH * PP],     g_suw_lo[HSH * PP];
DEV __nv_bfloat16 g_sdw_hi[PP * HSH],     g_sdw_lo[PP * HSH];
DEV __nv_bfloat16 g_m1_hi [HH * PP],      g_m1_lo [HH * PP];
DEV __nv_bfloat16 g_m2_hi [HH * HH],      g_m2_lo [HH * HH];
DEV int   g_counts[EE];
DEV int   g_slot_token[EE * CAP];
DEV int   g_pair_slot[B_TOK * 2];
DEV float g_pair_gate[B_TOK * 2];

__device__ __forceinline__ float silu_f(float x) { return x / (1.0f + expf(-x)); }

// ---------------- stage fill: A 128 rows, B 256 rows, 64B/row, hi+lo ----------------
__device__ __forceinline__ void fill_stage(uint32_t st, int tid,
    const char* Ah, const char* Al, const char* Bh, const char* Bl,
    size_t Kb, long rowA0, long rowB0, size_t kByte)
{
#pragma unroll
    for (int i = 0; i < 2; i++) {                  // A: 128 rows x 4 chunks
        int p = tid + (i << 8);
        int row = p >> 2, ch = p & 3;
        uint32_t d = st + row * ROWB + ch * 16;
        size_t s = (size_t)(rowA0 + row) * Kb + kByte + ch * 16;
        CP16(d + OFF_AH, Ah + s);
        CP16(d + OFF_AL, Al + s);
    }
#pragma unroll
    for (int i = 0; i < 4; i++) {                  // B: 256 rows x 4 chunks
        int p = tid + (i << 8);
        int row = p >> 2, ch = p & 3;
        uint32_t d = st + row * ROWB + ch * 16;
        size_t s = (size_t)(rowB0 + row) * Kb + kByte + ch * 16;
        CP16(d + OFF_BH, Bh + s);
        CP16(d + OFF_BL, Bl + s);
    }
    CP_COMMIT();
}

// ---------------- bf16-split x3 GEMM on mma.sync, warp tile 64x64 ----------------
// C[M,N] = epi(A[M,K] @ B[N,K]^T + bias);  MODE: 0=+bias 1=silu 2=*extra 3=+extra
template<int MODE>
__global__ __launch_bounds__(256, 1)
void mm_gemm(const __nv_bfloat16* __restrict__ Ahi, const __nv_bfloat16* __restrict__ Alo,
             const __nv_bfloat16* __restrict__ Bhi, const __nv_bfloat16* __restrict__ Blo,
             const float* __restrict__ bias, const float* __restrict__ extra,
             float* __restrict__ C32, __nv_bfloat16* __restrict__ Chi,
             __nv_bfloat16* __restrict__ Clo,
             const int* __restrict__ counts, int capRows, int N, int K)
{
    const int z  = blockIdx.z;
    const int m0 = blockIdx.y * BM;
    const int n0 = blockIdx.x * BN;
    int cnt = capRows;
    if (counts) { cnt = counts[z]; if (m0 >= cnt) return; }

    extern __shared__ __align__(128) char smem[];
    const uint32_t sb = smem_u32(smem);
    const int tid = threadIdx.x, lane = tid & 31, wid = tid >> 5;
    const int warp_m = wid & 1;        // 2 warps over M (64 rows)
    const int warp_n = wid >> 1;       // 4 warps over N (64 cols)

    const size_t Kb = (size_t)K * 2;
    const long rowA0 = (long)z * capRows + m0;
    const long rowB0 = (long)z * N + n0;
    const int  C = K / BKC;

    float acc[4][8][4];
#pragma unroll
    for (int i = 0; i < 4; i++)
#pragma unroll
        for (int j = 0; j < 8; j++)
#pragma unroll
            for (int q = 0; q < 4; q++) acc[i][j][q] = 0.f;

    const char* Ah = (const char*)Ahi; const char* Al = (const char*)Alo;
    const char* Bh = (const char*)Bhi; const char* Bl = (const char*)Blo;

    fill_stage(sb, tid, Ah, Al, Bh, Bl, Kb, rowA0, rowB0, 0);
    if (C > 1) fill_stage(sb + STAGE_BYTES, tid, Ah, Al, Bh, Bl, Kb, rowA0, rowB0, 64);

    const int lm = lane & 15;
    const int lkb = (lane >> 4) << 4;

    for (int c = 0; c < C; c++) {
        if (c + 2 < C) asm volatile("cp.async.wait_group 1;" ::: "memory");
        else           asm volatile("cp.async.wait_group 0;" ::: "memory");
        __syncthreads();
        if (c + 2 < C)
            fill_stage(sb + ((c + 2) % NSTAGE) * STAGE_BYTES, tid, Ah, Al, Bh, Bl,
                       Kb, rowA0, rowB0, (size_t)(c + 2) * 64);

        const uint32_t stg = sb + (c % NSTAGE) * STAGE_BYTES;
#pragma unroll
        for (int kk = 0; kk < 2; kk++) {
            const uint32_t kb = kk * 32 + lkb;
            uint32_t a_h[4][4], a_l[4][4], b_h[4][4], b_l[4][4];
#pragma unroll
            for (int mt = 0; mt < 4; mt++) {
                uint32_t ad = stg + (warp_m * 64 + mt * 16 + lm) * ROWB + kb;
                LDSM4(a_h[mt], ad + OFF_AH);
                LDSM4(a_l[mt], ad + OFF_AL);
            }
#pragma unroll
            for (int nt2 = 0; nt2 < 4; nt2++) {
                uint32_t bd = stg + (warp_n * 64 + nt2 * 16 + lm) * ROWB + kb;
                LDSM4(b_h[nt2], bd + OFF_BH);
                LDSM4(b_l[nt2], bd + OFF_BL);
            }
#pragma unroll
            for (int mt = 0; mt < 4; mt++)
#pragma unroll
                for (int nt = 0; nt < 8; nt++) {
                    const int n2 = nt >> 1, o = nt & 1;
                    MMA_BF16(acc[mt][nt], a_h[mt], b_h[n2][o], b_h[n2][o + 2]);
                    MMA_BF16(acc[mt][nt], a_h[mt], b_l[n2][o], b_l[n2][o + 2]);
                    MMA_BF16(acc[mt][nt], a_l[mt], b_h[n2][o], b_h[n2][o + 2]);
                }
        }
    }

    // ---- epilogue: registers -> gmem ----
    const float* biasz = bias + (size_t)z * N;
#pragma unroll
    for (int mt = 0; mt < 4; mt++) {
#pragma unroll
        for (int half = 0; half < 2; half++) {
            const int rtile = warp_m * 64 + mt * 16 + (lane >> 2) + half * 8;
            if (m0 + rtile >= cnt) continue;
            const size_t gr = (size_t)z * capRows + m0 + rtile;
#pragma unroll
            for (int nt = 0; nt < 8; nt++) {
                const int col = n0 + warp_n * 64 + nt * 8 + (lane & 3) * 2;
                float v0 = acc[mt][nt][half * 2 + 0] + biasz[col];
                float v1 = acc[mt][nt][half * 2 + 1] + biasz[col + 1];
                if (MODE == 1) { v0 = silu_f(v0); v1 = silu_f(v1); }
                if (MODE == 2) {
                    const float2 e = *(const float2*)&extra[gr * N + col];
                    v0 *= e.x; v1 *= e.y;
                }
                if (MODE == 3) {
                    const float2 e = *(const float2*)&extra[gr * N + col];
                    v0 += e.x; v1 += e.y;
                }
                if (C32) { float2 w = {v0, v1}; *(float2*)&C32[gr * N + col] = w; }
                if (Chi) {
                    __nv_bfloat16 h0 = __float2bfloat16(v0);
                    __nv_bfloat16 h1 = __float2bfloat16(v1);
                    __nv_bfloat162 hp; hp.x = h0; hp.y = h1;
                    *(__nv_bfloat162*)&Chi[gr * N + col] = hp;
                    __nv_bfloat162 lp;
                    lp.x = __float2bfloat16(v0 - __bfloat162float(h0));
                    lp.y = __float2bfloat16(v1 - __bfloat162float(h1));
                    *(__nv_bfloat162*)&Clo[gr * N + col] = lp;
                }
            }
        }
    }
}

// ---------------- small kernels ----------------
__global__ void conv_split_k(const float* __restrict__ in, __nv_bfloat16* __restrict__ hi,
                             __nv_bfloat16* __restrict__ lo, size_t n)
{
    size_t i = (size_t)blockIdx.x * blockDim.x + threadIdx.x;
    if (i >= n) return;
    float v = in[i];
    __nv_bfloat16 h = __float2bfloat16(v);
    hi[i] = h;
    lo[i] = __float2bfloat16(v - __bfloat162float(h));
}

// W [z, K, N] row-major -> out [(z*N + n), k]  (transpose + split)
__global__ void convT_k(const float* __restrict__ W, __nv_bfloat16* __restrict__ hi,
                        __nv_bfloat16* __restrict__ lo, int K, int N)
{
    __shared__ float t[32][33];
    const int n0 = blockIdx.x * 32, k0 = blockIdx.y * 32;
    const float* Wz = W + (size_t)blockIdx.z * K * N;
    for (int i = threadIdx.y; i < 32; i += 8)
        t[i][threadIdx.x] = Wz[(size_t)(k0 + i) * N + n0 + threadIdx.x];
    __syncthreads();
    for (int i = threadIdx.y; i < 32; i += 8) {
        size_t o = ((size_t)blockIdx.z * N + n0 + i) * K + k0 + threadIdx.x;
        float v = t[threadIdx.x][i];
        __nv_bfloat16 h = __float2bfloat16(v);
        hi[o] = h;
        lo[o] = __float2bfloat16(v - __bfloat162float(h));
    }
}

__global__ void zero_counts_k(int* counts) { if (threadIdx.x < EE) counts[threadIdx.x] = 0; }

__global__ void router_k(const float* __restrict__ p, const float* __restrict__ Wg,
                         int* __restrict__ counts, int* __restrict__ slot_token,
                         int* __restrict__ pair_slot, float* __restrict__ pair_gate)
{
    const int t = blockIdx.x;
    const int tid = threadIdx.x; // 128
    __shared__ float red[EE][128];
    float acc[EE];
#pragma unroll
    for (int e = 0; e < EE; e++) acc[e] = 0.f;
    const float* pr = p + (size_t)t * PP;
    for (int j = tid; j < PP; j += 128) {
        float pv = pr[j];
        const float* wg = Wg + (size_t)j * EE;
#pragma unroll
        for (int e = 0; e < EE; e++) acc[e] += pv * wg[e];
    }
#pragma unroll
    for (int e = 0; e < EE; e++) red[e][tid] = acc[e];
    __syncthreads();
    if (tid == 0) {
        float logit[EE];
        for (int e = 0; e < EE; e++) {
            float s = 0.f;
            for (int i = 0; i < 128; i++) s += red[e][i];
            logit[e] = s;
        }
        int i0 = 0;
        for (int e = 1; e < EE; e++) if (logit[e] > logit[i0]) i0 = e;
        int i1 = (i0 == 0) ? 1 : 0;
        for (int e = 0; e < EE; e++) {
            if (e == i0) continue;
            if (logit[e] > logit[i1]) i1 = e;
        }
        float g0 = 1.f / (1.f + expf(logit[i1] - logit[i0]));
        float g1 = 1.f - g0;
        int s0 = atomicAdd(&counts[i0], 1);
        int s1 = atomicAdd(&counts[i1], 1);
        slot_token[i0 * CAP + s0] = t;
        slot_token[i1 * CAP + s1] = t;
        pair_slot[2 * t]     = i0 * CAP + s0;
        pair_slot[2 * t + 1] = i1 * CAP + s1;
        pair_gate[2 * t]     = g0;
        pair_gate[2 * t + 1] = g1;
    }
}

__global__ void pack_k(const __nv_bfloat16* __restrict__ ph, const __nv_bfloat16* __restrict__ pl,
                       const int* __restrict__ stok, const int* __restrict__ counts,
                       __nv_bfloat16* __restrict__ aph, __nv_bfloat16* __restrict__ apl)
{
    const int slot = blockIdx.x;
    const int e = slot >> 12;
    if ((slot & (CAP - 1)) >= counts[e]) return;
    const int tok = stok[slot];
    const float4* s1 = (const float4*)(ph + (size_t)tok * PP);
    const float4* s2 = (const float4*)(pl + (size_t)tok * PP);
    float4* d1 = (float4*)(aph + (size_t)slot * PP);
    float4* d2 = (float4*)(apl + (size_t)slot * PP);
    const int t = threadIdx.x;
    d1[t] = s1[t];
    d2[t] = s2[t];
}

__global__ void combine_k(const float* __restrict__ eo, const int* __restrict__ pair_slot,
                          const float* __restrict__ pair_gate, float* __restrict__ moe)
{
    int idx = blockIdx.x * blockDim.x + threadIdx.x;
    if (idx >= B_TOK * PP) return;
    int t = idx >> 10, j = idx & (PP - 1);
    int s0 = pair_slot[2 * t], s1 = pair_slot[2 * t + 1];
    float g0 = pair_gate[2 * t], g1 = pair_gate[2 * t + 1];
    moe[idx] = g0 * eo[(size_t)s0 * PP + j] + g1 * eo[(size_t)s1 * PP + j];
}

__global__ __launch_bounds__(256)
void head_k(const float* __restrict__ hid2, const float* __restrict__ head_w,
            const float* __restrict__ head_b, float* __restrict__ out)
{
    const int t = blockIdx.x, tid = threadIdx.x;
    const int lane = tid & 31, warp = tid >> 5;
    __shared__ float row[HH];
    for (int i = tid; i < HH; i += 256) row[i] = hid2[(size_t)t * HH + i];
    __syncthreads();
#pragma unroll
    for (int oo = 0; oo < 4; oo++) {
        int o = warp + oo * 8;
        if (o >= OUTN) break;
        float s = 0.f;
        for (int i = lane; i < HH; i += 32) s += row[i] * head_w[(size_t)i * OUTN + o];
#pragma unroll
        for (int off = 16; off > 0; off >>= 1) s += __shfl_down_sync(0xFFFFFFFFu, s, off);
        if (lane == 0) out[(size_t)t * OUTN + o] = s + head_b[o];
    }
}

// ---------------- launch ----------------
template <typename T>
static T* symaddr(const void* sym) { void* p = nullptr; cudaGetSymbolAddress(&p, sym); return (T*)p; }

extern "C" void kernel_launch(void* const* d_in, const int* in_sizes, int n_in,
                              void* d_out, int out_size)
{
    const float* x      = (const float*)d_in[0];
    const float* Wproj  = (const float*)d_in[1];
    const float* bproj  = (const float*)d_in[2];
    const float* Wg     = (const float*)d_in[3];
    const float* W1     = (const float*)d_in[4];
    const float* b1     = (const float*)d_in[5];
    const float* W2     = (const float*)d_in[6];
    const float* b2     = (const float*)d_in[7];
    const float* sg_w   = (const float*)d_in[8];
    const float* sg_b   = (const float*)d_in[9];
    const float* su_w   = (const float*)d_in[10];
    const float* su_b   = (const float*)d_in[11];
    const float* sd_w   = (const float*)d_in[12];
    const float* sd_b   = (const float*)d_in[13];
    const float* m1_w   = (const float*)d_in[14];
    const float* m1_b   = (const float*)d_in[15];
    const float* m2_w   = (const float*)d_in[16];
    const float* m2_b   = (const float*)d_in[17];
    const float* head_w = (const float*)d_in[18];
    const float* head_b = (const float*)d_in[19];
    float* out = (float*)d_out;

    static bool attr_done = false;
    if (!attr_done) {
        cudaFuncSetAttribute(mm_gemm<0>, cudaFuncAttributeMaxDynamicSharedMemorySize, SMEM_BYTES);
        cudaFuncSetAttribute(mm_gemm<1>, cudaFuncAttributeMaxDynamicSharedMemorySize, SMEM_BYTES);
        cudaFuncSetAttribute(mm_gemm<2>, cudaFuncAttributeMaxDynamicSharedMemorySize, SMEM_BYTES);
        cudaFuncSetAttribute(mm_gemm<3>, cudaFuncAttributeMaxDynamicSharedMemorySize, SMEM_BYTES);
        attr_done = true;
    }

    __nv_bfloat16 *x_hi = symaddr<__nv_bfloat16>(g_x_hi),  *x_lo = symaddr<__nv_bfloat16>(g_x_lo);
    __nv_bfloat16 *p_hi = symaddr<__nv_bfloat16>(g_p_hi),  *p_lo = symaddr<__nv_bfloat16>(g_p_lo);
    float *p32  = symaddr<float>(g_p32);
    __nv_bfloat16 *ap_hi = symaddr<__nv_bfloat16>(g_ap_hi), *ap_lo = symaddr<__nv_bfloat16>(g_ap_lo);
    __nv_bfloat16 *h_hi  = symaddr<__nv_bfloat16>(g_h_hi),  *h_lo  = symaddr<__nv_bfloat16>(g_h_lo);
    float *eo32 = symaddr<float>(g_eo32);
    float *moe  = symaddr<float>(g_moe);
    float *sg32 = symaddr<float>(g_sg32);
    __nv_bfloat16 *su_hi = symaddr<__nv_bfloat16>(g_su_hi), *su_lo = symaddr<__nv_bfloat16>(g_su_lo);
    __nv_bfloat16 *cb_hi = symaddr<__nv_bfloat16>(g_cb_hi), *cb_lo = symaddr<__nv_bfloat16>(g_cb_lo);
    __nv_bfloat16 *h1_hi = symaddr<__nv_bfloat16>(g_h1_hi), *h1_lo = symaddr<__nv_bfloat16>(g_h1_lo);
    float *h232 = symaddr<float>(g_h232);
    __nv_bfloat16 *wp_hi = symaddr<__nv_bfloat16>(g_wp_hi), *wp_lo = symaddr<__nv_bfloat16>(g_wp_lo);
    __nv_bfloat16 *w1_hi = symaddr<__nv_bfloat16>(g_w1_hi), *w1_lo = symaddr<__nv_bfloat16>(g_w1_lo);
    __nv_bfloat16 *w2_hi = symaddr<__nv_bfloat16>(g_w2_hi), *w2_lo = symaddr<__nv_bfloat16>(g_w2_lo);
    __nv_bfloat16 *sgw_hi = symaddr<__nv_bfloat16>(g_sgw_hi), *sgw_lo = symaddr<__nv_bfloat16>(g_sgw_lo);
    __nv_bfloat16 *suw_hi = symaddr<__nv_bfloat16>(g_suw_hi), *suw_lo = symaddr<__nv_bfloat16>(g_suw_lo);
    __nv_bfloat16 *sdw_hi = symaddr<__nv_bfloat16>(g_sdw_hi), *sdw_lo = symaddr<__nv_bfloat16>(g_sdw_lo);
    __nv_bfloat16 *m1_hi = symaddr<__nv_bfloat16>(g_m1_hi), *m1_lo = symaddr<__nv_bfloat16>(g_m1_lo);
    __nv_bfloat16 *m2_hi = symaddr<__nv_bfloat16>(g_m2_hi), *m2_lo = symaddr<__nv_bfloat16>(g_m2_lo);
    int *counts = symaddr<int>(g_counts);
    int *stok   = symaddr<int>(g_slot_token);
    int *pslot  = symaddr<int>(g_pair_slot);
    float *pgate = symaddr<float>(g_pair_gate);

    // ---- split inputs / transpose+split weights ----
    conv_split_k<<<(B_TOK * DIN + 255) / 256, 256>>>(x, x_hi, x_lo, (size_t)B_TOK * DIN);
    convT_k<<<dim3(PP / 32, DIN / 32, 1),  dim3(32, 8)>>>(Wproj, wp_hi, wp_lo, DIN, PP);
    convT_k<<<dim3(HH / 32, PP / 32, EE),  dim3(32, 8)>>>(W1, w1_hi, w1_lo, PP, HH);
    convT_k<<<dim3(PP / 32, HH / 32, EE),  dim3(32, 8)>>>(W2, w2_hi, w2_lo, HH, PP);
    convT_k<<<dim3(HSH / 32, PP / 32, 1),  dim3(32, 8)>>>(sg_w, sgw_hi, sgw_lo, PP, HSH);
    convT_k<<<dim3(HSH / 32, PP / 32, 1),  dim3(32, 8)>>>(su_w, suw_hi, suw_lo, PP, HSH);
    convT_k<<<dim3(PP / 32, HSH / 32, 1),  dim3(32, 8)>>>(sd_w, sdw_hi, sdw_lo, HSH, PP);
    convT_k<<<dim3(HH / 32, PP / 32, 1),   dim3(32, 8)>>>(m1_w, m1_hi, m1_lo, PP, HH);
    convT_k<<<dim3(HH / 32, HH / 32, 1),   dim3(32, 8)>>>(m2_w, m2_hi, m2_lo, HH, HH);

    // 1. p = x @ Wproj + bproj
    mm_gemm<0><<<dim3(PP / BN, B_TOK / BM, 1), 256, SMEM_BYTES>>>(
        x_hi, x_lo, wp_hi, wp_lo, bproj, nullptr, p32, p_hi, p_lo,
        nullptr, B_TOK, PP, DIN);
    // 2. router + pack
    zero_counts_k<<<1, 32>>>(counts);
    router_k<<<B_TOK, 128>>>(p32, Wg, counts, stok, pslot, pgate);
    pack_k<<<EE * CAP, 128>>>(p_hi, p_lo, stok, counts, ap_hi, ap_lo);
    // 3. expert fc1
    mm_gemm<1><<<dim3(HH / BN, CAP / BM, EE), 256, SMEM_BYTES>>>(
        ap_hi, ap_lo, w1_hi, w1_lo, b1, nullptr, nullptr, h_hi, h_lo,
        counts, CAP, HH, PP);
    // 4. expert fc2
    mm_gemm<0><<<dim3(PP / BN, CAP / BM, EE), 256, SMEM_BYTES>>>(
        h_hi, h_lo, w2_hi, w2_lo, b2, nullptr, eo32, nullptr, nullptr,
        counts, CAP, PP, HH);
    // 5. combine
    combine_k<<<(B_TOK * PP + 255) / 256, 256>>>(eo32, pslot, pgate, moe);
    // 6. shared SwiGLU
    mm_gemm<1><<<dim3(HSH / BN, B_TOK / BM, 1), 256, SMEM_BYTES>>>(
        p_hi, p_lo, sgw_hi, sgw_lo, sg_b, nullptr, sg32, nullptr, nullptr,
        nullptr, B_TOK, HSH, PP);
    mm_gemm<2><<<dim3(HSH / BN, B_TOK / BM, 1), 256, SMEM_BYTES>>>(
        p_hi, p_lo, suw_hi, suw_lo, su_b, sg32, nullptr, su_hi, su_lo,
        nullptr, B_TOK, HSH, PP);
    // 7. down proj + moe residual
    mm_gemm<3><<<dim3(PP / BN, B_TOK / BM, 1), 256, SMEM_BYTES>>>(
        su_hi, su_lo, sdw_hi, sdw_lo, sd_b, moe, nullptr, cb_hi, cb_lo,
        nullptr, B_TOK, PP, HSH);
    // 8. output MLP
    mm_gemm<1><<<dim3(HH / BN, B_TOK / BM, 1), 256, SMEM_BYTES>>>(
        cb_hi, cb_lo, m1_hi, m1_lo, m1_b, nullptr, nullptr, h1_hi, h1_lo,
        nullptr, B_TOK, HH, PP);
    mm_gemm<0><<<dim3(HH / BN, B_TOK / BM, 1), 256, SMEM_BYTES>>>(
        h1_hi, h1_lo, m2_hi, m2_lo, m2_b, nullptr, h232, nullptr, nullptr,
        nullptr, B_TOK, HH, HH);
    // 9. head
    head_k<<<B_TOK, 256>>>(h232, head_w, head_b, out);
}

// round 6
// speedup vs baseline: 3.1051x; 1.0071x over previous
#include <cuda_runtime.h>
#include <cuda_bf16.h>
#include <math.h>
#include <stdint.h>

// ---------------- problem constants ----------------
#define B_TOK 4096
#define DIN   512
#define PP    1024
#define HH    2048
#define EE    8
#define HSH   4096
#define OUTN  29
#define CAP   4096

// ---------------- mma.sync GEMM tile config ----------------
#define BM 128
#define BN 256
#define BKC 32                     // bf16 k elems per chunk (64 bytes)
#define ROWB 80                    // smem row stride (64B data + 16B pad)
#define OFF_AH 0
#define OFF_AL (128 * ROWB)
#define OFF_BH (256 * ROWB)
#define OFF_BL (256 * ROWB + 256 * ROWB)
#define STAGE_BYTES (768 * ROWB)   // 61440
#define NSTAGE 3
#define SMEM_BYTES (NSTAGE * STAGE_BYTES) // 184320

// ---------------- PTX helpers ----------------
__device__ __forceinline__ uint32_t smem_u32(const void* p) {
    uint32_t a;
    asm("{ .reg .u64 t; cvta.to.shared.u64 t, %1; cvt.u32.u64 %0, t; }" : "=r"(a) : "l"(p));
    return a;
}
#define CP16(dst, src) asm volatile("cp.async.cg.shared.global [%0], [%1], 16;" :: "r"(dst), "l"(src) : "memory")
#define CP_COMMIT()    asm volatile("cp.async.commit_group;" ::: "memory")

#define LDSM4(r, addr) \
    asm volatile("ldmatrix.sync.aligned.m8n8.x4.shared.b16 {%0,%1,%2,%3}, [%4];" \
        : "=r"((r)[0]), "=r"((r)[1]), "=r"((r)[2]), "=r"((r)[3]) : "r"(addr))

#define MMA_BF16(c, a, b0, b1) \
    asm volatile("mma.sync.aligned.m16n8k16.row.col.f32.bf16.bf16.f32 " \
        "{%0,%1,%2,%3}, {%4,%5,%6,%7}, {%8,%9}, {%0,%1,%2,%3};" \
        : "+f"((c)[0]), "+f"((c)[1]), "+f"((c)[2]), "+f"((c)[3]) \
        : "r"((a)[0]), "r"((a)[1]), "r"((a)[2]), "r"((a)[3]), "r"(b0), "r"(b1))

// ---------------- scratch (device globals) ----------------
#define DEV __device__ __align__(128)
DEV __nv_bfloat16 g_x_hi [B_TOK * DIN],   g_x_lo [B_TOK * DIN];
DEV __nv_bfloat16 g_p_hi [B_TOK * PP],    g_p_lo [B_TOK * PP];
DEV float         g_p32  [B_TOK * PP];
DEV __nv_bfloat16 g_ap_hi[EE * CAP * PP], g_ap_lo[EE * CAP * PP];
DEV __nv_bfloat16 g_h_hi [EE * CAP * HH], g_h_lo [EE * CAP * HH];
DEV float         g_eo32 [EE * CAP * PP];
DEV float         g_moe  [B_TOK * PP];
DEV float         g_sg32 [B_TOK * HSH];
DEV __nv_bfloat16 g_su_hi[B_TOK * HSH],   g_su_lo[B_TOK * HSH];
DEV __nv_bfloat16 g_cb_hi[B_TOK * PP],    g_cb_lo[B_TOK * PP];
DEV __nv_bfloat16 g_h1_hi[B_TOK * HH],    g_h1_lo[B_TOK * HH];
DEV float         g_h232 [B_TOK * HH];
DEV __nv_bfloat16 g_wp_hi [PP * DIN],     g_wp_lo [PP * DIN];
DEV __nv_bfloat16 g_w1_hi [EE * HH * PP], g_w1_lo [EE * HH * PP];
DEV __nv_bfloat16 g_w2_hi [EE * PP * HH], g_w2_lo [EE * PP * HH];
DEV __nv_bfloat16 g_sgw_hi[HSH * PP],     g_sgw_lo[HSH * PP];
DEV __nv_bfloat16 g_suw_hi[HSH * PP],     g_suw_lo[HSH * PP];
DEV __nv_bfloat16 g_sdw_hi[PP * HSH],     g_sdw_lo[PP * HSH];
DEV __nv_bfloat16 g_m1_hi [HH * PP],      g_m1_lo [HH * PP];
DEV __nv_bfloat16 g_m2_hi [HH * HH],      g_m2_lo [HH * HH];
DEV int   g_counts[EE];
DEV int   g_slot_token[EE * CAP];
DEV int   g_pair_slot[B_TOK * 2];
DEV float g_pair_gate[B_TOK * 2];

__device__ __forceinline__ float silu_f(float x) { return x / (1.0f + expf(-x)); }

// ---------------- stage fill: A 128 rows, B 256 rows, 64B/row, hi+lo ----------------
__device__ __forceinline__ void fill_stage(uint32_t st, int tid,
    const char* Ah, const char* Al, const char* Bh, const char* Bl,
    size_t Kb, long rowA0, long rowB0, size_t kByte)
{
#pragma unroll
    for (int i = 0; i < 2; i++) {                  // A: 128 rows x 4 chunks
        int p = tid + (i << 8);
        int row = p >> 2, ch = p & 3;
        uint32_t d = st + row * ROWB + ch * 16;
        size_t s = (size_t)(rowA0 + row) * Kb + kByte + ch * 16;
        CP16(d + OFF_AH, Ah + s);
        CP16(d + OFF_AL, Al + s);
    }
#pragma unroll
    for (int i = 0; i < 4; i++) {                  // B: 256 rows x 4 chunks
        int p = tid + (i << 8);
        int row = p >> 2, ch = p & 3;
        uint32_t d = st + row * ROWB + ch * 16;
        size_t s = (size_t)(rowB0 + row) * Kb + kByte + ch * 16;
        CP16(d + OFF_BH, Bh + s);
        CP16(d + OFF_BL, Bl + s);
    }
    CP_COMMIT();
}

// ---------------- bf16-split x3 GEMM on mma.sync, warp tile 64x64 ----------------
// Pass-major MMA ordering: accumulator reuse distance = 32 instructions
// (was 1 in r5 -> RAW-latency-bound).  MODE: 0=+bias 1=silu 2=*extra 3=+extra
template<int MODE>
__global__ __launch_bounds__(256, 1)
void mm_gemm(const __nv_bfloat16* __restrict__ Ahi, const __nv_bfloat16* __restrict__ Alo,
             const __nv_bfloat16* __restrict__ Bhi, const __nv_bfloat16* __restrict__ Blo,
             const float* __restrict__ bias, const float* __restrict__ extra,
             float* __restrict__ C32, __nv_bfloat16* __restrict__ Chi,
             __nv_bfloat16* __restrict__ Clo,
             const int* __restrict__ counts, int capRows, int N, int K)
{
    const int z  = blockIdx.z;
    const int m0 = blockIdx.y * BM;
    const int n0 = blockIdx.x * BN;
    int cnt = capRows;
    if (counts) { cnt = counts[z]; if (m0 >= cnt) return; }

    extern __shared__ __align__(128) char smem[];
    const uint32_t sb = smem_u32(smem);
    const int tid = threadIdx.x, lane = tid & 31, wid = tid >> 5;
    const int warp_m = wid & 1;        // 2 warps over M (64 rows)
    const int warp_n = wid >> 1;       // 4 warps over N (64 cols)

    const size_t Kb = (size_t)K * 2;
    const long rowA0 = (long)z * capRows + m0;
    const long rowB0 = (long)z * N + n0;
    const int  C = K / BKC;

    float acc[4][8][4];
#pragma unroll
    for (int i = 0; i < 4; i++)
#pragma unroll
        for (int j = 0; j < 8; j++)
#pragma unroll
            for (int q = 0; q < 4; q++) acc[i][j][q] = 0.f;

    const char* Ah = (const char*)Ahi; const char* Al = (const char*)Alo;
    const char* Bh = (const char*)Bhi; const char* Bl = (const char*)Blo;

    fill_stage(sb, tid, Ah, Al, Bh, Bl, Kb, rowA0, rowB0, 0);
    if (C > 1) fill_stage(sb + STAGE_BYTES, tid, Ah, Al, Bh, Bl, Kb, rowA0, rowB0, 64);

    const int lm = lane & 15;
    const int lkb = (lane >> 4) << 4;

    for (int c = 0; c < C; c++) {
        if (c + 2 < C) asm volatile("cp.async.wait_group 1;" ::: "memory");
        else           asm volatile("cp.async.wait_group 0;" ::: "memory");
        __syncthreads();
        if (c + 2 < C)
            fill_stage(sb + ((c + 2) % NSTAGE) * STAGE_BYTES, tid, Ah, Al, Bh, Bl,
                       Kb, rowA0, rowB0, (size_t)(c + 2) * 64);

        const uint32_t stg = sb + (c % NSTAGE) * STAGE_BYTES;
#pragma unroll
        for (int kk = 0; kk < 2; kk++) {
            const uint32_t kb = kk * 32 + lkb;
            uint32_t a_h[4][4], a_l[4][4], b_h[4][4], b_l[4][4];
#pragma unroll
            for (int mt = 0; mt < 4; mt++) {
                uint32_t ad = stg + (warp_m * 64 + mt * 16 + lm) * ROWB + kb;
                LDSM4(a_h[mt], ad + OFF_AH);
                LDSM4(a_l[mt], ad + OFF_AL);
            }
#pragma unroll
            for (int nt2 = 0; nt2 < 4; nt2++) {
                uint32_t bd = stg + (warp_n * 64 + nt2 * 16 + lm) * ROWB + kb;
                LDSM4(b_h[nt2], bd + OFF_BH);
                LDSM4(b_l[nt2], bd + OFF_BL);
            }
            // pass 1: hi x hi  (32 independent MMAs)
#pragma unroll
            for (int mt = 0; mt < 4; mt++)
#pragma unroll
                for (int nt = 0; nt < 8; nt++) {
                    const int n2 = nt >> 1, o = nt & 1;
                    MMA_BF16(acc[mt][nt], a_h[mt], b_h[n2][o], b_h[n2][o + 2]);
                }
            // pass 2: hi x lo
#pragma unroll
            for (int mt = 0; mt < 4; mt++)
#pragma unroll
                for (int nt = 0; nt < 8; nt++) {
                    const int n2 = nt >> 1, o = nt & 1;
                    MMA_BF16(acc[mt][nt], a_h[mt], b_l[n2][o], b_l[n2][o + 2]);
                }
            // pass 3: lo x hi
#pragma unroll
            for (int mt = 0; mt < 4; mt++)
#pragma unroll
                for (int nt = 0; nt < 8; nt++) {
                    const int n2 = nt >> 1, o = nt & 1;
                    MMA_BF16(acc[mt][nt], a_l[mt], b_h[n2][o], b_h[n2][o + 2]);
                }
        }
    }

    // ---- epilogue: registers -> gmem ----
    const float* biasz = bias + (size_t)z * N;
#pragma unroll
    for (int mt = 0; mt < 4; mt++) {
#pragma unroll
        for (int half = 0; half < 2; half++) {
            const int rtile = warp_m * 64 + mt * 16 + (lane >> 2) + half * 8;
            if (m0 + rtile >= cnt) continue;
            const size_t gr = (size_t)z * capRows + m0 + rtile;
#pragma unroll
            for (int nt = 0; nt < 8; nt++) {
                const int col = n0 + warp_n * 64 + nt * 8 + (lane & 3) * 2;
                float v0 = acc[mt][nt][half * 2 + 0] + biasz[col];
                float v1 = acc[mt][nt][half * 2 + 1] + biasz[col + 1];
                if (MODE == 1) { v0 = silu_f(v0); v1 = silu_f(v1); }
                if (MODE == 2) {
                    const float2 e = *(const float2*)&extra[gr * N + col];
                    v0 *= e.x; v1 *= e.y;
                }
                if (MODE == 3) {
                    const float2 e = *(const float2*)&extra[gr * N + col];
                    v0 += e.x; v1 += e.y;
                }
                if (C32) { float2 w = {v0, v1}; *(float2*)&C32[gr * N + col] = w; }
                if (Chi) {
                    __nv_bfloat16 h0 = __float2bfloat16(v0);
                    __nv_bfloat16 h1 = __float2bfloat16(v1);
                    __nv_bfloat162 hp; hp.x = h0; hp.y = h1;
                    *(__nv_bfloat162*)&Chi[gr * N + col] = hp;
                    __nv_bfloat162 lp;
                    lp.x = __float2bfloat16(v0 - __bfloat162float(h0));
                    lp.y = __float2bfloat16(v1 - __bfloat162float(h1));
                    *(__nv_bfloat162*)&Clo[gr * N + col] = lp;
                }
            }
        }
    }
}

// ---------------- small kernels ----------------
__global__ void conv_split_k(const float* __restrict__ in, __nv_bfloat16* __restrict__ hi,
                             __nv_bfloat16* __restrict__ lo, size_t n)
{
    size_t i = (size_t)blockIdx.x * blockDim.x + threadIdx.x;
    if (i >= n) return;
    float v = in[i];
    __nv_bfloat16 h = __float2bfloat16(v);
    hi[i] = h;
    lo[i] = __float2bfloat16(v - __bfloat162float(h));
}

// W [z, K, N] row-major -> out [(z*N + n), k]  (transpose + split)
__global__ void convT_k(const float* __restrict__ W, __nv_bfloat16* __restrict__ hi,
                        __nv_bfloat16* __restrict__ lo, int K, int N)
{
    __shared__ float t[32][33];
    const int n0 = blockIdx.x * 32, k0 = blockIdx.y * 32;
    const float* Wz = W + (size_t)blockIdx.z * K * N;
    for (int i = threadIdx.y; i < 32; i += 8)
        t[i][threadIdx.x] = Wz[(size_t)(k0 + i) * N + n0 + threadIdx.x];
    __syncthreads();
    for (int i = threadIdx.y; i < 32; i += 8) {
        size_t o = ((size_t)blockIdx.z * N + n0 + i) * K + k0 + threadIdx.x;
        float v = t[threadIdx.x][i];
        __nv_bfloat16 h = __float2bfloat16(v);
        hi[o] = h;
        lo[o] = __float2bfloat16(v - __bfloat162float(h));
    }
}

__global__ void zero_counts_k(int* counts) { if (threadIdx.x < EE) counts[threadIdx.x] = 0; }

__global__ void router_k(const float* __restrict__ p, const float* __restrict__ Wg,
                         int* __restrict__ counts, int* __restrict__ slot_token,
                         int* __restrict__ pair_slot, float* __restrict__ pair_gate)
{
    const int t = blockIdx.x;
    const int tid = threadIdx.x; // 128
    __shared__ float red[EE][128];
    float acc[EE];
#pragma unroll
    for (int e = 0; e < EE; e++) acc[e] = 0.f;
    const float* pr = p + (size_t)t * PP;
    for (int j = tid; j < PP; j += 128) {
        float pv = pr[j];
        const float* wg = Wg + (size_t)j * EE;
#pragma unroll
        for (int e = 0; e < EE; e++) acc[e] += pv * wg[e];
    }
#pragma unroll
    for (int e = 0; e < EE; e++) red[e][tid] = acc[e];
    __syncthreads();
    if (tid == 0) {
        float logit[EE];
        for (int e = 0; e < EE; e++) {
            float s = 0.f;
            for (int i = 0; i < 128; i++) s += red[e][i];
            logit[e] = s;
        }
        int i0 = 0;
        for (int e = 1; e < EE; e++) if (logit[e] > logit[i0]) i0 = e;
        int i1 = (i0 == 0) ? 1 : 0;
        for (int e = 0; e < EE; e++) {
            if (e == i0) continue;
            if (logit[e] > logit[i1]) i1 = e;
        }
        float g0 = 1.f / (1.f + expf(logit[i1] - logit[i0]));
        float g1 = 1.f - g0;
        int s0 = atomicAdd(&counts[i0], 1);
        int s1 = atomicAdd(&counts[i1], 1);
        slot_token[i0 * CAP + s0] = t;
        slot_token[i1 * CAP + s1] = t;
        pair_slot[2 * t]     = i0 * CAP + s0;
        pair_slot[2 * t + 1] = i1 * CAP + s1;
        pair_gate[2 * t]     = g0;
        pair_gate[2 * t + 1] = g1;
    }
}

__global__ void pack_k(const __nv_bfloat16* __restrict__ ph, const __nv_bfloat16* __restrict__ pl,
                       const int* __restrict__ stok, const int* __restrict__ counts,
                       __nv_bfloat16* __restrict__ aph, __nv_bfloat16* __restrict__ apl)
{
    const int slot = blockIdx.x;
    const int e = slot >> 12;
    if ((slot & (CAP - 1)) >= counts[e]) return;
    const int tok = stok[slot];
    const float4* s1 = (const float4*)(ph + (size_t)tok * PP);
    const float4* s2 = (const float4*)(pl + (size_t)tok * PP);
    float4* d1 = (float4*)(aph + (size_t)slot * PP);
    float4* d2 = (float4*)(apl + (size_t)slot * PP);
    const int t = threadIdx.x;
    d1[t] = s1[t];
    d2[t] = s2[t];
}

__global__ void combine_k(const float* __restrict__ eo, const int* __restrict__ pair_slot,
                          const float* __restrict__ pair_gate, float* __restrict__ moe)
{
    int idx = blockIdx.x * blockDim.x + threadIdx.x;
    if (idx >= B_TOK * PP) return;
    int t = idx >> 10, j = idx & (PP - 1);
    int s0 = pair_slot[2 * t], s1 = pair_slot[2 * t + 1];
    float g0 = pair_gate[2 * t], g1 = pair_gate[2 * t + 1];
    moe[idx] = g0 * eo[(size_t)s0 * PP + j] + g1 * eo[(size_t)s1 * PP + j];
}

__global__ __launch_bounds__(256)
void head_k(const float* __restrict__ hid2, const float* __restrict__ head_w,
            const float* __restrict__ head_b, float* __restrict__ out)
{
    const int t = blockIdx.x, tid = threadIdx.x;
    const int lane = tid & 31, warp = tid >> 5;
    __shared__ float row[HH];
    for (int i = tid; i < HH; i += 256) row[i] = hid2[(size_t)t * HH + i];
    __syncthreads();
#pragma unroll
    for (int oo = 0; oo < 4; oo++) {
        int o = warp + oo * 8;
        if (o >= OUTN) break;
        float s = 0.f;
        for (int i = lane; i < HH; i += 32) s += row[i] * head_w[(size_t)i * OUTN + o];
#pragma unroll
        for (int off = 16; off > 0; off >>= 1) s += __shfl_down_sync(0xFFFFFFFFu, s, off);
        if (lane == 0) out[(size_t)t * OUTN + o] = s + head_b[o];
    }
}

// ---------------- launch ----------------
template <typename T>
static T* symaddr(const void* sym) { void* p = nullptr; cudaGetSymbolAddress(&p, sym); return (T*)p; }

extern "C" void kernel_launch(void* const* d_in, const int* in_sizes, int n_in,
                              void* d_out, int out_size)
{
    const float* x      = (const float*)d_in[0];
    const float* Wproj  = (const float*)d_in[1];
    const float* bproj  = (const float*)d_in[2];
    const float* Wg     = (const float*)d_in[3];
    const float* W1     = (const float*)d_in[4];
    const float* b1     = (const float*)d_in[5];
    const float* W2     = (const float*)d_in[6];
    const float* b2     = (const float*)d_in[7];
    const float* sg_w   = (const float*)d_in[8];
    const float* sg_b   = (const float*)d_in[9];
    const float* su_w   = (const float*)d_in[10];
    const float* su_b   = (const float*)d_in[11];
    const float* sd_w   = (const float*)d_in[12];
    const float* sd_b   = (const float*)d_in[13];
    const float* m1_w   = (const float*)d_in[14];
    const float* m1_b   = (const float*)d_in[15];
    const float* m2_w   = (const float*)d_in[16];
    const float* m2_b   = (const float*)d_in[17];
    const float* head_w = (const float*)d_in[18];
    const float* head_b = (const float*)d_in[19];
    float* out = (float*)d_out;

    static bool attr_done = false;
    if (!attr_done) {
        cudaFuncSetAttribute(mm_gemm<0>, cudaFuncAttributeMaxDynamicSharedMemorySize, SMEM_BYTES);
        cudaFuncSetAttribute(mm_gemm<1>, cudaFuncAttributeMaxDynamicSharedMemorySize, SMEM_BYTES);
        cudaFuncSetAttribute(mm_gemm<2>, cudaFuncAttributeMaxDynamicSharedMemorySize, SMEM_BYTES);
        cudaFuncSetAttribute(mm_gemm<3>, cudaFuncAttributeMaxDynamicSharedMemorySize, SMEM_BYTES);
        attr_done = true;
    }

    __nv_bfloat16 *x_hi = symaddr<__nv_bfloat16>(g_x_hi),  *x_lo = symaddr<__nv_bfloat16>(g_x_lo);
    __nv_bfloat16 *p_hi = symaddr<__nv_bfloat16>(g_p_hi),  *p_lo = symaddr<__nv_bfloat16>(g_p_lo);
    float *p32  = symaddr<float>(g_p32);
    __nv_bfloat16 *ap_hi = symaddr<__nv_bfloat16>(g_ap_hi), *ap_lo = symaddr<__nv_bfloat16>(g_ap_lo);
    __nv_bfloat16 *h_hi  = symaddr<__nv_bfloat16>(g_h_hi),  *h_lo  = symaddr<__nv_bfloat16>(g_h_lo);
    float *eo32 = symaddr<float>(g_eo32);
    float *moe  = symaddr<float>(g_moe);
    float *sg32 = symaddr<float>(g_sg32);
    __nv_bfloat16 *su_hi = symaddr<__nv_bfloat16>(g_su_hi), *su_lo = symaddr<__nv_bfloat16>(g_su_lo);
    __nv_bfloat16 *cb_hi = symaddr<__nv_bfloat16>(g_cb_hi), *cb_lo = symaddr<__nv_bfloat16>(g_cb_lo);
    __nv_bfloat16 *h1_hi = symaddr<__nv_bfloat16>(g_h1_hi), *h1_lo = symaddr<__nv_bfloat16>(g_h1_lo);
    float *h232 = symaddr<float>(g_h232);
    __nv_bfloat16 *wp_hi = symaddr<__nv_bfloat16>(g_wp_hi), *wp_lo = symaddr<__nv_bfloat16>(g_wp_lo);
    __nv_bfloat16 *w1_hi = symaddr<__nv_bfloat16>(g_w1_hi), *w1_lo = symaddr<__nv_bfloat16>(g_w1_lo);
    __nv_bfloat16 *w2_hi = symaddr<__nv_bfloat16>(g_w2_hi), *w2_lo = symaddr<__nv_bfloat16>(g_w2_lo);
    __nv_bfloat16 *sgw_hi = symaddr<__nv_bfloat16>(g_sgw_hi), *sgw_lo = symaddr<__nv_bfloat16>(g_sgw_lo);
    __nv_bfloat16 *suw_hi = symaddr<__nv_bfloat16>(g_suw_hi), *suw_lo = symaddr<__nv_bfloat16>(g_suw_lo);
    __nv_bfloat16 *sdw_hi = symaddr<__nv_bfloat16>(g_sdw_hi), *sdw_lo = symaddr<__nv_bfloat16>(g_sdw_lo);
    __nv_bfloat16 *m1_hi = symaddr<__nv_bfloat16>(g_m1_hi), *m1_lo = symaddr<__nv_bfloat16>(g_m1_lo);
    __nv_bfloat16 *m2_hi = symaddr<__nv_bfloat16>(g_m2_hi), *m2_lo = symaddr<__nv_bfloat16>(g_m2_lo);
    int *counts = symaddr<int>(g_counts);
    int *stok   = symaddr<int>(g_slot_token);
    int *pslot  = symaddr<int>(g_pair_slot);
    float *pgate = symaddr<float>(g_pair_gate);

    // ---- split inputs / transpose+split weights ----
    conv_split_k<<<(B_TOK * DIN + 255) / 256, 256>>>(x, x_hi, x_lo, (size_t)B_TOK * DIN);
    convT_k<<<dim3(PP / 32, DIN / 32, 1),  dim3(32, 8)>>>(Wproj, wp_hi, wp_lo, DIN, PP);
    convT_k<<<dim3(HH / 32, PP / 32, EE),  dim3(32, 8)>>>(W1, w1_hi, w1_lo, PP, HH);
    convT_k<<<dim3(PP / 32, HH / 32, EE),  dim3(32, 8)>>>(W2, w2_hi, w2_lo, HH, PP);
    convT_k<<<dim3(HSH / 32, PP / 32, 1),  dim3(32, 8)>>>(sg_w, sgw_hi, sgw_lo, PP, HSH);
    convT_k<<<dim3(HSH / 32, PP / 32, 1),  dim3(32, 8)>>>(su_w, suw_hi, suw_lo, PP, HSH);
    convT_k<<<dim3(PP / 32, HSH / 32, 1),  dim3(32, 8)>>>(sd_w, sdw_hi, sdw_lo, HSH, PP);
    convT_k<<<dim3(HH / 32, PP / 32, 1),   dim3(32, 8)>>>(m1_w, m1_hi, m1_lo, PP, HH);
    convT_k<<<dim3(HH / 32, HH / 32, 1),   dim3(32, 8)>>>(m2_w, m2_hi, m2_lo, HH, HH);

    // 1. p = x @ Wproj + bproj
    mm_gemm<0><<<dim3(PP / BN, B_TOK / BM, 1), 256, SMEM_BYTES>>>(
        x_hi, x_lo, wp_hi, wp_lo, bproj, nullptr, p32, p_hi, p_lo,
        nullptr, B_TOK, PP, DIN);
    // 2. router + pack
    zero_counts_k<<<1, 32>>>(counts);
    router_k<<<B_TOK, 128>>>(p32, Wg, counts, stok, pslot, pgate);
    pack_k<<<EE * CAP, 128>>>(p_hi, p_lo, stok, counts, ap_hi, ap_lo);
    // 3. expert fc1
    mm_gemm<1><<<dim3(HH / BN, CAP / BM, EE), 256, SMEM_BYTES>>>(
        ap_hi, ap_lo, w1_hi, w1_lo, b1, nullptr, nullptr, h_hi, h_lo,
        counts, CAP, HH, PP);
    // 4. expert fc2
    mm_gemm<0><<<dim3(PP / BN, CAP / BM, EE), 256, SMEM_BYTES>>>(
        h_hi, h_lo, w2_hi, w2_lo, b2, nullptr, eo32, nullptr, nullptr,
        counts, CAP, PP, HH);
    // 5. combine
    combine_k<<<(B_TOK * PP + 255) / 256, 256>>>(eo32, pslot, pgate, moe);
    // 6. shared SwiGLU
    mm_gemm<1><<<dim3(HSH / BN, B_TOK / BM, 1), 256, SMEM_BYTES>>>(
        p_hi, p_lo, sgw_hi, sgw_lo, sg_b, nullptr, sg32, nullptr, nullptr,
        nullptr, B_TOK, HSH, PP);
    mm_gemm<2><<<dim3(HSH / BN, B_TOK / BM, 1), 256, SMEM_BYTES>>>(
        p_hi, p_lo, suw_hi, suw_lo, su_b, sg32, nullptr, su_hi, su_lo,
        nullptr, B_TOK, HSH, PP);
    // 7. down proj + moe residual
    mm_gemm<3><<<dim3(PP / BN, B_TOK / BM, 1), 256, SMEM_BYTES>>>(
        su_hi, su_lo, sdw_hi, sdw_lo, sd_b, moe, nullptr, cb_hi, cb_lo,
        nullptr, B_TOK, PP, HSH);
    // 8. output MLP
    mm_gemm<1><<<dim3(HH / BN, B_TOK / BM, 1), 256, SMEM_BYTES>>>(
        cb_hi, cb_lo, m1_hi, m1_lo, m1_b, nullptr, nullptr, h1_hi, h1_lo,
        nullptr, B_TOK, HH, PP);
    mm_gemm<0><<<dim3(HH / BN, B_TOK / BM, 1), 256, SMEM_BYTES>>>(
        h1_hi, h1_lo, m2_hi, m2_lo, m2_b, nullptr, h232, nullptr, nullptr,
        nullptr, B_TOK, HH, HH);
    // 9. head
    head_k<<<B_TOK, 256>>>(h232, head_w, head_b, out);
}